// round 1
// baseline (speedup 1.0000x reference)
#include <cuda_runtime.h>
#include <math.h>

#define BB 4
#define SS 2048
#define HH 768
#define NH 12
#define DD 64
#define M_TOT (BB*SS)      /* 8192 */
#define N4H (4*HH)         /* 3072 */

// ---------------- scratch (static device globals; no allocs) ----------------
__device__ float g_proj[(size_t)M_TOT * N4H];      // [8192][3072] : U|V|Q|K
__device__ float g_Qt[(size_t)BB*NH*DD*SS];        // [bh][d][s]
__device__ float g_Kt[(size_t)BB*NH*DD*SS];        // [bh][d][s]
__device__ float g_V [(size_t)BB*NH*SS*DD];        // [bh][s][d]
__device__ float g_attn[(size_t)M_TOT * HH];       // [8192][768]
__device__ float g_gated[(size_t)M_TOT * HH];      // [8192][768]
__device__ float g_cos[SS*DD];
__device__ float g_sin[SS*DD];

// ---------------- RoPE tables ----------------
__global__ void rope_table_kernel() {
    int s = blockIdx.x;
    int d = threadIdx.x;          // 0..63
    int p = d & 31;
    double inv = pow(10000.0, -((double)(2 * p)) / 64.0);
    float theta = (float)s * (float)inv;      // fp32 quantized like reference
    double t = (double)theta;
    g_cos[s*DD + d] = (float)cos(t);
    g_sin[s*DD + d] = (float)sin(t);
}

// ---------------- fp32 tiled GEMM: C[M,N] = A[M,K] @ B[K,N] + bias (+res) ----
// mode 0: A = Aext (x), C = g_proj          (proj GEMM)
// mode 1: A = g_gated, C = Cext, res added  (out GEMM)
__global__ void __launch_bounds__(256, 2) gemm_kernel(
    const float* __restrict__ Aext, const float* __restrict__ Bw,
    const float* __restrict__ bias, const float* __restrict__ res,
    float* __restrict__ Cext, int M, int N, int K, int mode)
{
    __shared__ float As[16][128];
    __shared__ float Bs[16][128];

    const float* A = mode ? g_gated : Aext;
    float* C       = mode ? Cext    : g_proj;

    const int bm = blockIdx.y * 128;
    const int bn = blockIdx.x * 128;
    const int tid = threadIdx.x;
    const int tx = tid & 15;          // col group
    const int ty = tid >> 4;          // row group

    const int ar = tid >> 2;          // 0..63
    const int ac = (tid & 3) << 2;    // 0,4,8,12
    const int br = tid >> 5;          // 0..7
    const int bc = (tid & 31) << 2;   // 0..124

    float acc[8][8];
#pragma unroll
    for (int i = 0; i < 8; i++)
#pragma unroll
        for (int j = 0; j < 8; j++) acc[i][j] = 0.f;

    for (int k0 = 0; k0 < K; k0 += 16) {
        float4 a0 = *(const float4*)(A + (size_t)(bm + ar)      * K + k0 + ac);
        float4 a1 = *(const float4*)(A + (size_t)(bm + ar + 64) * K + k0 + ac);
        float4 b0 = *(const float4*)(Bw + (size_t)(k0 + br)     * N + bn + bc);
        float4 b1 = *(const float4*)(Bw + (size_t)(k0 + br + 8) * N + bn + bc);

        As[ac+0][ar] = a0.x; As[ac+1][ar] = a0.y; As[ac+2][ar] = a0.z; As[ac+3][ar] = a0.w;
        As[ac+0][ar+64] = a1.x; As[ac+1][ar+64] = a1.y; As[ac+2][ar+64] = a1.z; As[ac+3][ar+64] = a1.w;
        *(float4*)&Bs[br][bc]   = b0;
        *(float4*)&Bs[br+8][bc] = b1;
        __syncthreads();

#pragma unroll
        for (int kk = 0; kk < 16; kk++) {
            float ra[8], rb[8];
            *(float4*)(ra)     = *(float4*)&As[kk][ty*8];
            *(float4*)(ra + 4) = *(float4*)&As[kk][ty*8 + 4];
            *(float4*)(rb)     = *(float4*)&Bs[kk][tx*8];
            *(float4*)(rb + 4) = *(float4*)&Bs[kk][tx*8 + 4];
#pragma unroll
            for (int i = 0; i < 8; i++)
#pragma unroll
                for (int j = 0; j < 8; j++)
                    acc[i][j] += ra[i] * rb[j];
        }
        __syncthreads();
    }

#pragma unroll
    for (int i = 0; i < 8; i++) {
        int row = bm + ty*8 + i;
#pragma unroll
        for (int j = 0; j < 8; j += 4) {
            int col = bn + tx*8 + j;
            float4 bv = *(const float4*)(bias + col);
            float4 o;
            o.x = acc[i][j+0] + bv.x;
            o.y = acc[i][j+1] + bv.y;
            o.z = acc[i][j+2] + bv.z;
            o.w = acc[i][j+3] + bv.w;
            if (mode) {
                float4 rv = *(const float4*)(res + (size_t)row * N + col);
                o.x += rv.x; o.y += rv.y; o.z += rv.z; o.w += rv.w;
            }
            *(float4*)(C + (size_t)row * N + col) = o;
        }
    }
}

// ---------------- RoPE + layout transform ----------------
// grid: (S/64, B*NH). Writes g_Qt/g_Kt d-major, g_V s-major.
__global__ void __launch_bounds__(256) rope_kernel()
{
    __shared__ float sq[64][65];
    __shared__ float sk[64][65];

    const int bh = blockIdx.y;
    const int b  = bh / NH;
    const int h  = bh % NH;
    const int s0 = blockIdx.x * 64;
    const int tid = threadIdx.x;
    const int d4 = (tid & 15) * 4;   // 0..60
    const int r0 = tid >> 4;         // 0..15

#pragma unroll
    for (int rep = 0; rep < 4; rep++) {
        int sl = r0 + rep * 16;
        int s  = s0 + sl;
        size_t base = ((size_t)(b * SS + s)) * N4H + h * DD;
        float4 q  = *(const float4*)(g_proj + base + 2*HH + d4);
        float4 k  = *(const float4*)(g_proj + base + 3*HH + d4);
        float4 v  = *(const float4*)(g_proj + base +   HH + d4);
        int dp = (d4 < 32) ? d4 + 32 : d4 - 32;
        float sgn = (d4 < 32) ? -1.f : 1.f;
        float4 qp = *(const float4*)(g_proj + base + 2*HH + dp);
        float4 kp = *(const float4*)(g_proj + base + 3*HH + dp);
        float4 cs = *(const float4*)(g_cos + s*DD + d4);
        float4 sn = *(const float4*)(g_sin + s*DD + d4);

        // V pass-through (transpose [b,s,h,d] -> [bh,s,d])
        *(float4*)(g_V + ((size_t)bh * SS + s) * DD + d4) = v;

        sq[d4+0][sl] = q.x * cs.x + sgn * qp.x * sn.x;
        sq[d4+1][sl] = q.y * cs.y + sgn * qp.y * sn.y;
        sq[d4+2][sl] = q.z * cs.z + sgn * qp.z * sn.z;
        sq[d4+3][sl] = q.w * cs.w + sgn * qp.w * sn.w;

        sk[d4+0][sl] = k.x * cs.x + sgn * kp.x * sn.x;
        sk[d4+1][sl] = k.y * cs.y + sgn * kp.y * sn.y;
        sk[d4+2][sl] = k.z * cs.z + sgn * kp.z * sn.z;
        sk[d4+3][sl] = k.w * cs.w + sgn * kp.w * sn.w;
    }
    __syncthreads();

#pragma unroll
    for (int rep = 0; rep < 4; rep++) {
        int drow = r0 + rep * 16;
        int s4 = d4;  // reuse (tid&15)*4 as s offset
        float4 oq, ok;
        oq.x = sq[drow][s4+0]; oq.y = sq[drow][s4+1]; oq.z = sq[drow][s4+2]; oq.w = sq[drow][s4+3];
        ok.x = sk[drow][s4+0]; ok.y = sk[drow][s4+1]; ok.z = sk[drow][s4+2]; ok.w = sk[drow][s4+3];
        *(float4*)(g_Qt + ((size_t)bh * DD + drow) * SS + s0 + s4) = oq;
        *(float4*)(g_Kt + ((size_t)bh * DD + drow) * SS + s0 + s4) = ok;
    }
}

// ---------------- fused causal sigmoid attention ----------------
// grid: (S/64 q-blocks, B*NH). 64x64 tiles, 256 threads (16x16, 4x4 each).
__global__ void __launch_bounds__(256) attn_kernel()
{
    __shared__ float Qs[64][64];   // [d][q]
    __shared__ float KS[64][64];   // K as [d][k], then reused as S[q][k]
    __shared__ float Vs[64][64];   // [k][d]

    const int bh = blockIdx.y;
    const int qb = blockIdx.x;
    const int tid = threadIdx.x;
    const int tx = tid & 15;
    const int ty = tid >> 4;
    const int c4 = (tid & 15) * 4;
    const int r0 = tid >> 4;

#pragma unroll
    for (int rep = 0; rep < 4; rep++) {
        int d = r0 + rep * 16;
        *(float4*)&Qs[d][c4] =
            *(const float4*)(g_Qt + ((size_t)bh * DD + d) * SS + qb * 64 + c4);
    }

    float acc[4][4];
#pragma unroll
    for (int i = 0; i < 4; i++)
#pragma unroll
        for (int j = 0; j < 4; j++) acc[i][j] = 0.f;

    const float scale = 0.125f;  // 64^-0.5

    for (int kt = 0; kt <= qb; kt++) {
        __syncthreads();   // guard KS/Vs reuse from previous iteration (and Qs fill)
#pragma unroll
        for (int rep = 0; rep < 4; rep++) {
            int d = r0 + rep * 16;
            *(float4*)&KS[d][c4] =
                *(const float4*)(g_Kt + ((size_t)bh * DD + d) * SS + kt * 64 + c4);
            int k = d;
            *(float4*)&Vs[k][c4] =
                *(const float4*)(g_V + ((size_t)bh * SS + kt * 64 + k) * DD + c4);
        }
        __syncthreads();

        float sacc[4][4];
#pragma unroll
        for (int i = 0; i < 4; i++)
#pragma unroll
            for (int j = 0; j < 4; j++) sacc[i][j] = 0.f;

#pragma unroll
        for (int kk = 0; kk < 64; kk++) {
            float a[4], bb[4];
            *(float4*)a  = *(float4*)&Qs[kk][ty*4];
            *(float4*)bb = *(float4*)&KS[kk][tx*4];
#pragma unroll
            for (int i = 0; i < 4; i++)
#pragma unroll
                for (int j = 0; j < 4; j++)
                    sacc[i][j] += a[i] * bb[j];
        }
        __syncthreads();   // all reads of K done before overwriting as S

        const bool diag = (kt == qb);
#pragma unroll
        for (int i = 0; i < 4; i++) {
            float4 sp;
            float* spp = &sp.x;
#pragma unroll
            for (int j = 0; j < 4; j++) {
                float sc = sacc[i][j] * scale;
                float p = 1.f / (1.f + expf(-sc));
                if (diag && (tx*4 + j > ty*4 + i)) p = 0.f;
                spp[j] = p;
            }
            *(float4*)&KS[ty*4 + i][tx*4] = sp;
        }
        __syncthreads();

#pragma unroll
        for (int t = 0; t < 64; t++) {
            float vv[4];
            *(float4*)vv = *(float4*)&Vs[t][tx*4];
#pragma unroll
            for (int i = 0; i < 4; i++) {
                float sv = KS[ty*4 + i][t];
#pragma unroll
                for (int j = 0; j < 4; j++)
                    acc[i][j] += sv * vv[j];
            }
        }
    }

    const int b = bh / NH;
    const int h = bh % NH;
#pragma unroll
    for (int i = 0; i < 4; i++) {
        int s = qb * 64 + ty*4 + i;
        float4 o;
        o.x = acc[i][0]; o.y = acc[i][1]; o.z = acc[i][2]; o.w = acc[i][3];
        *(float4*)(g_attn + ((size_t)(b * SS + s)) * HH + h * DD + tx*4) = o;
    }
}

// ---------------- LayerNorm + SiLU gate ----------------
__device__ __forceinline__ float block_reduce_sum(float v, float* red)
{
    int lane = threadIdx.x & 31;
    int wid  = threadIdx.x >> 5;
#pragma unroll
    for (int o = 16; o > 0; o >>= 1) v += __shfl_xor_sync(0xffffffffu, v, o);
    if (lane == 0) red[wid] = v;
    __syncthreads();
    float r = (lane < 8) ? red[lane] : 0.f;
    if (wid == 0) {
#pragma unroll
        for (int o = 4; o > 0; o >>= 1) r += __shfl_xor_sync(0xffffffffu, r, o);
        if (lane == 0) red[0] = r;
    }
    __syncthreads();
    float out = red[0];
    __syncthreads();
    return out;
}

__global__ void __launch_bounds__(256) ln_gate_kernel(
    const float* __restrict__ gamma, const float* __restrict__ beta)
{
    __shared__ float sm[HH];
    __shared__ float red[32];
    const int row = blockIdx.x;
    const int tid = threadIdx.x;

    float loc = 0.f;
#pragma unroll
    for (int k = 0; k < 3; k++) {
        int i = tid + k * 256;
        float v = g_attn[(size_t)row * HH + i];
        sm[i] = v;
        loc += v;
    }
    float mu = block_reduce_sum(loc, red) * (1.f / HH);

    float loc2 = 0.f;
#pragma unroll
    for (int k = 0; k < 3; k++) {
        int i = tid + k * 256;
        float d = sm[i] - mu;
        loc2 += d * d;
    }
    float var = block_reduce_sum(loc2, red) * (1.f / HH);
    float rstd = rsqrtf(var + 1e-8f);

#pragma unroll
    for (int k = 0; k < 3; k++) {
        int i = tid + k * 256;
        float ln = (sm[i] - mu) * rstd * gamma[i] + beta[i];
        float u = g_proj[(size_t)row * N4H + i];   // U = first quarter
        float silu = u / (1.f + expf(-u));
        g_gated[(size_t)row * HH + i] = silu * ln;
    }
}

// ---------------- launch ----------------
extern "C" void kernel_launch(void* const* d_in, const int* in_sizes, int n_in,
                              void* d_out, int out_size)
{
    const float* x      = (const float*)d_in[0];
    // d_in[1] = attn_mask (causal tril bool) — structure hardcoded
    const float* W_proj = (const float*)d_in[2];
    const float* b_proj = (const float*)d_in[3];
    const float* gamma  = (const float*)d_in[4];
    const float* beta   = (const float*)d_in[5];
    const float* W_out  = (const float*)d_in[6];
    const float* b_out  = (const float*)d_in[7];
    float* out = (float*)d_out;

    // 1. RoPE tables
    rope_table_kernel<<<SS, DD>>>();

    // 2. proj = x @ W_proj + b_proj   [8192,768]@[768,3072]
    gemm_kernel<<<dim3(N4H/128, M_TOT/128), 256>>>(
        x, W_proj, b_proj, nullptr, nullptr, M_TOT, N4H, HH, 0);

    // 3. RoPE + transpose into attention layouts
    rope_kernel<<<dim3(SS/64, BB*NH), 256>>>();

    // 4. fused causal sigmoid attention
    attn_kernel<<<dim3(SS/64, BB*NH), 256>>>();

    // 5. LayerNorm + SiLU(U) gate
    ln_gate_kernel<<<M_TOT, 256>>>(gamma, beta);

    // 6. out = residual + gated @ W_out + b_out
    gemm_kernel<<<dim3(HH/128, M_TOT/128), 256>>>(
        x, W_out, b_out, x, out, M_TOT, HH, HH, 1);
}

// round 8
// speedup vs baseline: 1.0293x; 1.0293x over previous
#include <cuda_runtime.h>
#include <math.h>
#include <stdint.h>

#define BB 4
#define SS 2048
#define HH 768
#define NH 12
#define DD 64
#define M_TOT (BB*SS)      /* 8192 */
#define N4H (4*HH)         /* 3072 */

typedef unsigned long long u64;

// ---------------- scratch (round-1 layout: proven delta=0) ------------------
__device__ float g_proj[(size_t)M_TOT * N4H];      // [8192][3072] : U|V|Q|K
__device__ float g_Qt[(size_t)BB*NH*DD*SS];        // [bh][d][s]
__device__ float g_Kt[(size_t)BB*NH*DD*SS];        // [bh][d][s]
__device__ float g_V [(size_t)BB*NH*SS*DD];        // [bh][s][d]
__device__ float g_attn[(size_t)M_TOT * HH];       // [8192][768]
__device__ float g_gated[(size_t)M_TOT * HH];      // [8192][768]
__device__ float g_cos[SS*DD];
__device__ float g_sin[SS*DD];

// ---------------- packed f32x2 helpers (Blackwell FFMA2, plain sm_100) ------
#define PACK2(u, lo, hi) \
    asm("mov.b64 %0, {%1, %2};" : "=l"(u) : "f"(lo), "f"(hi))
#define UNPACK2(lo, hi, u) \
    asm("mov.b64 {%0, %1}, %2;" : "=f"(lo), "=f"(hi) : "l"(u))
#define FMA2(d, a, b) \
    asm("fma.rn.f32x2 %0, %1, %2, %0;" : "+l"(d) : "l"(a), "l"(b))

// ---------------- RoPE tables ----------------
__global__ void rope_table_kernel() {
    int s = blockIdx.x;
    int d = threadIdx.x;          // 0..63
    int p = d & 31;
    double inv = pow(10000.0, -((double)(2 * p)) / 64.0);
    float theta = (float)s * (float)inv;      // fp32 quantized like reference
    double t = (double)theta;
    g_cos[s*DD + d] = (float)cos(t);
    g_sin[s*DD + d] = (float)sin(t);
}

// ---------------- fp32 tiled GEMM with packed-FMA2 inner loop ----------------
// mode 0: A = Aext (x), C = g_proj          (proj GEMM)
// mode 1: A = g_gated, C = Cext, res added  (out GEMM)
__global__ void __launch_bounds__(256) gemm_kernel(
    const float* __restrict__ Aext, const float* __restrict__ Bw,
    const float* __restrict__ bias, const float* __restrict__ res,
    float* __restrict__ Cext, int M, int N, int K, int mode)
{
    __shared__ float As[16][128];
    __shared__ float Bs[16][128];

    const float* A = mode ? g_gated : Aext;
    float* C       = mode ? Cext    : g_proj;

    const int bm = blockIdx.y * 128;
    const int bn = blockIdx.x * 128;
    const int tid = threadIdx.x;
    const int tx = tid & 15;          // col group
    const int ty = tid >> 4;          // row group

    const int ar = tid >> 2;          // 0..63
    const int ac = (tid & 3) << 2;    // 0,4,8,12
    const int br = tid >> 5;          // 0..7
    const int bc = (tid & 31) << 2;   // 0..124

    u64 acc2[8][4];                   // [row i][col pair jp] -> (c[i][2jp], c[i][2jp+1])
#pragma unroll
    for (int i = 0; i < 8; i++)
#pragma unroll
        for (int jp = 0; jp < 4; jp++) acc2[i][jp] = 0ull;   // bits of (0.f, 0.f)

    for (int k0 = 0; k0 < K; k0 += 16) {
        float4 a0 = *(const float4*)(A + (size_t)(bm + ar)      * K + k0 + ac);
        float4 a1 = *(const float4*)(A + (size_t)(bm + ar + 64) * K + k0 + ac);
        float4 b0 = *(const float4*)(Bw + (size_t)(k0 + br)     * N + bn + bc);
        float4 b1 = *(const float4*)(Bw + (size_t)(k0 + br + 8) * N + bn + bc);

        As[ac+0][ar] = a0.x; As[ac+1][ar] = a0.y; As[ac+2][ar] = a0.z; As[ac+3][ar] = a0.w;
        As[ac+0][ar+64] = a1.x; As[ac+1][ar+64] = a1.y; As[ac+2][ar+64] = a1.z; As[ac+3][ar+64] = a1.w;
        *(float4*)&Bs[br][bc]   = b0;
        *(float4*)&Bs[br+8][bc] = b1;
        __syncthreads();

#pragma unroll
        for (int kk = 0; kk < 16; kk++) {
            float ra[8], rbf[8];
            *(float4*)(ra)      = *(float4*)&As[kk][ty*8];
            *(float4*)(ra + 4)  = *(float4*)&As[kk][ty*8 + 4];
            *(float4*)(rbf)     = *(float4*)&Bs[kk][tx*8];
            *(float4*)(rbf + 4) = *(float4*)&Bs[kk][tx*8 + 4];
            u64 rb2[4];
            PACK2(rb2[0], rbf[0], rbf[1]);
            PACK2(rb2[1], rbf[2], rbf[3]);
            PACK2(rb2[2], rbf[4], rbf[5]);
            PACK2(rb2[3], rbf[6], rbf[7]);
#pragma unroll
            for (int i = 0; i < 8; i++) {
                u64 ad; PACK2(ad, ra[i], ra[i]);
#pragma unroll
                for (int jp = 0; jp < 4; jp++)
                    FMA2(acc2[i][jp], ad, rb2[jp]);
            }
        }
        __syncthreads();
    }

#pragma unroll
    for (int i = 0; i < 8; i++) {
        int row = bm + ty*8 + i;
#pragma unroll
        for (int jp = 0; jp < 4; jp += 2) {
            int col = bn + tx*8 + jp*2;
            float4 o;
            UNPACK2(o.x, o.y, acc2[i][jp]);
            UNPACK2(o.z, o.w, acc2[i][jp+1]);
            float4 bv = *(const float4*)(bias + col);
            o.x += bv.x; o.y += bv.y; o.z += bv.z; o.w += bv.w;
            if (mode) {
                float4 rv = *(const float4*)(res + (size_t)row * N + col);
                o.x += rv.x; o.y += rv.y; o.z += rv.z; o.w += rv.w;
            }
            *(float4*)(C + (size_t)row * N + col) = o;
        }
    }
}

// ---------------- RoPE + layout transform (round-1) ----------------
__global__ void __launch_bounds__(256) rope_kernel()
{
    __shared__ float sq[64][65];
    __shared__ float sk[64][65];

    const int bh = blockIdx.y;
    const int b  = bh / NH;
    const int h  = bh % NH;
    const int s0 = blockIdx.x * 64;
    const int tid = threadIdx.x;
    const int d4 = (tid & 15) * 4;   // 0..60
    const int r0 = tid >> 4;         // 0..15

#pragma unroll
    for (int rep = 0; rep < 4; rep++) {
        int sl = r0 + rep * 16;
        int s  = s0 + sl;
        size_t base = ((size_t)(b * SS + s)) * N4H + h * DD;
        float4 q  = *(const float4*)(g_proj + base + 2*HH + d4);
        float4 k  = *(const float4*)(g_proj + base + 3*HH + d4);
        float4 v  = *(const float4*)(g_proj + base +   HH + d4);
        int dp = (d4 < 32) ? d4 + 32 : d4 - 32;
        float sgn = (d4 < 32) ? -1.f : 1.f;
        float4 qp = *(const float4*)(g_proj + base + 2*HH + dp);
        float4 kp = *(const float4*)(g_proj + base + 3*HH + dp);
        float4 cs = *(const float4*)(g_cos + s*DD + d4);
        float4 sn = *(const float4*)(g_sin + s*DD + d4);

        *(float4*)(g_V + ((size_t)bh * SS + s) * DD + d4) = v;

        sq[d4+0][sl] = q.x * cs.x + sgn * qp.x * sn.x;
        sq[d4+1][sl] = q.y * cs.y + sgn * qp.y * sn.y;
        sq[d4+2][sl] = q.z * cs.z + sgn * qp.z * sn.z;
        sq[d4+3][sl] = q.w * cs.w + sgn * qp.w * sn.w;

        sk[d4+0][sl] = k.x * cs.x + sgn * kp.x * sn.x;
        sk[d4+1][sl] = k.y * cs.y + sgn * kp.y * sn.y;
        sk[d4+2][sl] = k.z * cs.z + sgn * kp.z * sn.z;
        sk[d4+3][sl] = k.w * cs.w + sgn * kp.w * sn.w;
    }
    __syncthreads();

#pragma unroll
    for (int rep = 0; rep < 4; rep++) {
        int drow = r0 + rep * 16;
        int s4 = d4;
        float4 oq, ok;
        oq.x = sq[drow][s4+0]; oq.y = sq[drow][s4+1]; oq.z = sq[drow][s4+2]; oq.w = sq[drow][s4+3];
        ok.x = sk[drow][s4+0]; ok.y = sk[drow][s4+1]; ok.z = sk[drow][s4+2]; ok.w = sk[drow][s4+3];
        *(float4*)(g_Qt + ((size_t)bh * DD + drow) * SS + s0 + s4) = oq;
        *(float4*)(g_Kt + ((size_t)bh * DD + drow) * SS + s0 + s4) = ok;
    }
}

// ---------------- fused causal sigmoid attention (f32x2 inner loops) --------
__global__ void __launch_bounds__(256) attn_kernel()
{
    __shared__ float Qs[64][64];   // [d][q]
    __shared__ float KS[64][64];   // K as [d][k], then reused as S[q][k]
    __shared__ float Vs[64][64];   // [k][d]

    const int bh = blockIdx.y;
    const int qb = blockIdx.x;
    const int tid = threadIdx.x;
    const int tx = tid & 15;
    const int ty = tid >> 4;
    const int c4 = (tid & 15) * 4;
    const int r0 = tid >> 4;

#pragma unroll
    for (int rep = 0; rep < 4; rep++) {
        int d = r0 + rep * 16;
        *(float4*)&Qs[d][c4] =
            *(const float4*)(g_Qt + ((size_t)bh * DD + d) * SS + qb * 64 + c4);
    }

    u64 acc2[4][2];                  // output accum pairs: (c[i][0],c[i][1]),(c[i][2],c[i][3])
#pragma unroll
    for (int i = 0; i < 4; i++) { acc2[i][0] = 0ull; acc2[i][1] = 0ull; }

    const float scale = 0.125f;

    for (int kt = 0; kt <= qb; kt++) {
        __syncthreads();   // guard KS/Vs reuse from previous iteration (and Qs fill)
#pragma unroll
        for (int rep = 0; rep < 4; rep++) {
            int d = r0 + rep * 16;
            *(float4*)&KS[d][c4] =
                *(const float4*)(g_Kt + ((size_t)bh * DD + d) * SS + kt * 64 + c4);
            int k = d;
            *(float4*)&Vs[k][c4] =
                *(const float4*)(g_V + ((size_t)bh * SS + kt * 64 + k) * DD + c4);
        }
        __syncthreads();

        u64 s2[4][2];
#pragma unroll
        for (int i = 0; i < 4; i++) { s2[i][0] = 0ull; s2[i][1] = 0ull; }

#pragma unroll
        for (int kk = 0; kk < 64; kk++) {
            float a[4];
            *(float4*)a = *(float4*)&Qs[kk][ty*4];
            float4 bb  = *(float4*)&KS[kk][tx*4];
            u64 bp0, bp1;
            PACK2(bp0, bb.x, bb.y);
            PACK2(bp1, bb.z, bb.w);
#pragma unroll
            for (int i = 0; i < 4; i++) {
                u64 ad; PACK2(ad, a[i], a[i]);
                FMA2(s2[i][0], ad, bp0);
                FMA2(s2[i][1], ad, bp1);
            }
        }
        __syncthreads();   // all reads of K done before overwriting as S

        const bool diag = (kt == qb);
#pragma unroll
        for (int i = 0; i < 4; i++) {
            float sacc0, sacc1, sacc2v, sacc3;
            UNPACK2(sacc0, sacc1, s2[i][0]);
            UNPACK2(sacc2v, sacc3, s2[i][1]);
            float4 sp;
            {
                float sc = sacc0 * scale;
                float p = __fdividef(1.f, 1.f + __expf(-sc));
                if (diag && (tx*4 + 0 > ty*4 + i)) p = 0.f;
                sp.x = p;
            }
            {
                float sc = sacc1 * scale;
                float p = __fdividef(1.f, 1.f + __expf(-sc));
                if (diag && (tx*4 + 1 > ty*4 + i)) p = 0.f;
                sp.y = p;
            }
            {
                float sc = sacc2v * scale;
                float p = __fdividef(1.f, 1.f + __expf(-sc));
                if (diag && (tx*4 + 2 > ty*4 + i)) p = 0.f;
                sp.z = p;
            }
            {
                float sc = sacc3 * scale;
                float p = __fdividef(1.f, 1.f + __expf(-sc));
                if (diag && (tx*4 + 3 > ty*4 + i)) p = 0.f;
                sp.w = p;
            }
            *(float4*)&KS[ty*4 + i][tx*4] = sp;
        }
        __syncthreads();

#pragma unroll
        for (int t = 0; t < 64; t++) {
            float4 vv = *(float4*)&Vs[t][tx*4];
            u64 vp0, vp1;
            PACK2(vp0, vv.x, vv.y);
            PACK2(vp1, vv.z, vv.w);
#pragma unroll
            for (int i = 0; i < 4; i++) {
                float sv = KS[ty*4 + i][t];
                u64 svd; PACK2(svd, sv, sv);
                FMA2(acc2[i][0], svd, vp0);
                FMA2(acc2[i][1], svd, vp1);
            }
        }
    }

    const int b = bh / NH;
    const int h = bh % NH;
#pragma unroll
    for (int i = 0; i < 4; i++) {
        int s = qb * 64 + ty*4 + i;
        float4 o;
        UNPACK2(o.x, o.y, acc2[i][0]);
        UNPACK2(o.z, o.w, acc2[i][1]);
        *(float4*)(g_attn + ((size_t)(b * SS + s)) * HH + h * DD + tx*4) = o;
    }
}

// ---------------- LayerNorm + SiLU gate (round-1 + fast math) ---------------
__device__ __forceinline__ float block_reduce_sum(float v, float* red)
{
    int lane = threadIdx.x & 31;
    int wid  = threadIdx.x >> 5;
#pragma unroll
    for (int o = 16; o > 0; o >>= 1) v += __shfl_xor_sync(0xffffffffu, v, o);
    if (lane == 0) red[wid] = v;
    __syncthreads();
    float r = (lane < 8) ? red[lane] : 0.f;
    if (wid == 0) {
#pragma unroll
        for (int o = 4; o > 0; o >>= 1) r += __shfl_xor_sync(0xffffffffu, r, o);
        if (lane == 0) red[0] = r;
    }
    __syncthreads();
    float out = red[0];
    __syncthreads();
    return out;
}

__global__ void __launch_bounds__(256) ln_gate_kernel(
    const float* __restrict__ gamma, const float* __restrict__ beta)
{
    __shared__ float sm[HH];
    __shared__ float red[32];
    const int row = blockIdx.x;
    const int tid = threadIdx.x;

    float loc = 0.f;
#pragma unroll
    for (int k = 0; k < 3; k++) {
        int i = tid + k * 256;
        float v = g_attn[(size_t)row * HH + i];
        sm[i] = v;
        loc += v;
    }
    float mu = block_reduce_sum(loc, red) * (1.f / HH);

    float loc2 = 0.f;
#pragma unroll
    for (int k = 0; k < 3; k++) {
        int i = tid + k * 256;
        float d = sm[i] - mu;
        loc2 += d * d;
    }
    float var = block_reduce_sum(loc2, red) * (1.f / HH);
    float rstd = rsqrtf(var + 1e-8f);

#pragma unroll
    for (int k = 0; k < 3; k++) {
        int i = tid + k * 256;
        float ln = (sm[i] - mu) * rstd * gamma[i] + beta[i];
        float u = g_proj[(size_t)row * N4H + i];   // U = first quarter
        float silu = __fdividef(u, 1.f + __expf(-u));
        g_gated[(size_t)row * HH + i] = silu * ln;
    }
}

// ---------------- launch ----------------
extern "C" void kernel_launch(void* const* d_in, const int* in_sizes, int n_in,
                              void* d_out, int out_size)
{
    const float* x      = (const float*)d_in[0];
    // d_in[1] = attn_mask (causal tril bool) — structure hardcoded
    const float* W_proj = (const float*)d_in[2];
    const float* b_proj = (const float*)d_in[3];
    const float* gamma  = (const float*)d_in[4];
    const float* beta   = (const float*)d_in[5];
    const float* W_out  = (const float*)d_in[6];
    const float* b_out  = (const float*)d_in[7];
    float* out = (float*)d_out;

    // 1. RoPE tables
    rope_table_kernel<<<SS, DD>>>();

    // 2. proj = x @ W_proj + b_proj   [8192,768]@[768,3072]
    gemm_kernel<<<dim3(N4H/128, M_TOT/128), 256>>>(
        x, W_proj, b_proj, nullptr, nullptr, M_TOT, N4H, HH, 0);

    // 3. RoPE + transpose into attention layouts
    rope_kernel<<<dim3(SS/64, BB*NH), 256>>>();

    // 4. fused causal sigmoid attention
    attn_kernel<<<dim3(SS/64, BB*NH), 256>>>();

    // 5. LayerNorm + SiLU(U) gate
    ln_gate_kernel<<<M_TOT, 256>>>(gamma, beta);

    // 6. out = residual + gated @ W_out + b_out
    gemm_kernel<<<dim3(HH/128, M_TOT/128), 256>>>(
        x, W_out, b_out, x, out, M_TOT, HH, HH, 1);
}